// round 7
// baseline (speedup 1.0000x reference)
#include <cuda_runtime.h>
#include <cuda_bf16.h>

#define THREADS 256
#define PSTRIDE 33       // float2 row stride: bankpair(c*33+r) = (c+r)%16

__device__ __forceinline__ float red8(float v) {
    v += __shfl_xor_sync(0xffffffffu, v, 1, 8);
    v += __shfl_xor_sync(0xffffffffu, v, 2, 8);
    v += __shfl_xor_sync(0xffffffffu, v, 4, 8);
    return v;
}
__device__ __forceinline__ float red32(float v) {
    #pragma unroll
    for (int o = 16; o > 0; o >>= 1) v += __shfl_xor_sync(0xffffffffu, v, o);
    return v;
}
__device__ __forceinline__ float sum4(const float4& v) {
    return (v.x + v.y) + (v.z + v.w);
}
__device__ __forceinline__ float pick4(const float4& v, int e) {
    return (e == 0) ? v.x : (e == 1) ? v.y : (e == 2) ? v.z : v.w;
}

__global__ __launch_bounds__(THREADS, 4)
void sym_equiv_kernel(const float* __restrict__ X,
                      const float* __restrict__ w,
                      float* __restrict__ out)
{
    // P[c][r] = (X[r][c], X[r+32][c]),  c in [0,64), r in [0,32)
    __shared__ float2 P[64 * PSTRIDE];
    __shared__ float Cvec[64];
    __shared__ __align__(16) float Tw[8];
    __shared__ __align__(16) float Dw[8];
    __shared__ float ws[15];

    const int t  = threadIdx.x;
    const int i1 = t >> 3;             // owns rows i1, i1+32
    const int q  = t & 7;
    const int ib = q << 2;             // owns cols [ib,ib+4) and [ib+32,ib+36)
    const int dq_own = i1 >> 2;        // octet lane holding the diagonal

    if (t < 15) ws[t] = w[t];

    const float* base1 = X + (size_t)blockIdx.x * 4096;
    const float* base2 = X + ((size_t)blockIdx.x + 512) * 4096;

    // ================= Matrix 1: Phase 1 =================
    float4 va0 = *(const float4*)(base1 + i1 * 64 + ib);
    float4 va1 = *(const float4*)(base1 + i1 * 64 + ib + 32);
    float4 vb0 = *(const float4*)(base1 + (i1 + 32) * 64 + ib);
    float4 vb1 = *(const float4*)(base1 + (i1 + 32) * 64 + ib + 32);

    {
        float2* p0 = P + (size_t)ib * PSTRIDE + i1;
        float2* p1 = P + (size_t)(ib + 32) * PSTRIDE + i1;
        p0[0*PSTRIDE] = make_float2(va0.x, vb0.x);
        p0[1*PSTRIDE] = make_float2(va0.y, vb0.y);
        p0[2*PSTRIDE] = make_float2(va0.z, vb0.z);
        p0[3*PSTRIDE] = make_float2(va0.w, vb0.w);
        p1[0*PSTRIDE] = make_float2(va1.x, vb1.x);
        p1[1*PSTRIDE] = make_float2(va1.y, vb1.y);
        p1[2*PSTRIDE] = make_float2(va1.z, vb1.z);
        p1[3*PSTRIDE] = make_float2(va1.w, vb1.w);
    }
    const float pa1 = sum4(va0) + sum4(va1);
    const float pb1 = sum4(vb0) + sum4(vb1);
    float r1a = red8(pa1), r1b = red8(pb1);
    const float xa1 = __shfl_sync(0xffffffffu, pick4(va0, i1 & 3), dq_own, 8);
    const float xb1 = __shfl_sync(0xffffffffu, pick4(vb1, i1 & 3), dq_own, 8);
    {
        float ps = red32(pa1 + pb1);
        float dd = red32((q == 0) ? (xa1 + xb1) : 0.f);
        if ((t & 31) == 0) { Tw[t >> 5] = ps; Dw[t >> 5] = dd; }
    }
    __syncthreads();                                   // bar 1

    // -------- prefetch Matrix 2 (latency hides behind m1 ph2/3) --------
    float4 ua0 = *(const float4*)(base2 + i1 * 64 + ib);
    float4 ua1 = *(const float4*)(base2 + i1 * 64 + ib + 32);
    float4 ub0 = *(const float4*)(base2 + (i1 + 32) * 64 + ib);
    float4 ub1 = *(const float4*)(base2 + (i1 + 32) * 64 + ib + 32);

    // ================= Matrix 1: Phase 2 =================
    const float w8v = ws[8], w6v = ws[6];
    float T, D;
    {
        const float4 t0 = *(const float4*)Tw, t1 = *(const float4*)(Tw + 4);
        const float4 d0 = *(const float4*)Dw, d1 = *(const float4*)(Dw + 4);
        T = sum4(t0) + sum4(t1);
        D = sum4(d0) + sum4(d1);
    }
    const float gT = ws[14]*T + ws[4]*D;
    const float gE = ws[11]*T + ws[2]*D;

    float r2a, r2b;
    {
        const float2* pa0 = P + (size_t)i1 * PSTRIDE + ib;
        const float2* pb0 = P + (size_t)(i1 + 32) * PSTRIDE + ib;
        float2 q0 = pa0[0], q1 = pa0[1], q2 = pa0[2], q3 = pa0[3];
        r2a = ((q0.x+q1.x)+(q2.x+q3.x)) + ((q0.y+q1.y)+(q2.y+q3.y));
        va0.x=w8v*va0.x+w6v*q0.x;  va1.x=w8v*va1.x+w6v*q0.y;
        va0.y=w8v*va0.y+w6v*q1.x;  va1.y=w8v*va1.y+w6v*q1.y;
        va0.z=w8v*va0.z+w6v*q2.x;  va1.z=w8v*va1.z+w6v*q2.y;
        va0.w=w8v*va0.w+w6v*q3.x;  va1.w=w8v*va1.w+w6v*q3.y;
        q0 = pb0[0]; q1 = pb0[1]; q2 = pb0[2]; q3 = pb0[3];
        r2b = ((q0.x+q1.x)+(q2.x+q3.x)) + ((q0.y+q1.y)+(q2.y+q3.y));
        vb0.x=w8v*vb0.x+w6v*q0.x;  vb1.x=w8v*vb1.x+w6v*q0.y;
        vb0.y=w8v*vb0.y+w6v*q1.x;  vb1.y=w8v*vb1.y+w6v*q1.y;
        vb0.z=w8v*vb0.z+w6v*q2.x;  vb1.z=w8v*vb1.z+w6v*q2.y;
        vb0.w=w8v*vb0.w+w6v*q3.x;  vb1.w=w8v*vb1.w+w6v*q3.y;
    }
    r2a = red8(r2a); r2b = red8(r2b);

    const float cA  = ws[12]*r1a + ws[13]*r2a + ws[3]*xa1 + gT;
    const float evA = ws[5] *r1a + ws[9] *r2a + ws[0]*xa1 + gE;
    const float cB  = ws[12]*r1b + ws[13]*r2b + ws[3]*xb1 + gT;
    const float evB = ws[5] *r1b + ws[9] *r2b + ws[0]*xb1 + gE;
    if (q == 0) {
        Cvec[i1]      = ws[7]*r1a + ws[10]*r2a + ws[1]*xa1;
        Cvec[i1 + 32] = ws[7]*r1b + ws[10]*r2b + ws[1]*xb1;
    }
    __syncthreads();                                   // bar 2 (all P reads done)

    // ====== Matrix 2: Phase 1 (reuses P) — overlapped with m1 output ======
    {
        float2* p0 = P + (size_t)ib * PSTRIDE + i1;
        float2* p1 = P + (size_t)(ib + 32) * PSTRIDE + i1;
        p0[0*PSTRIDE] = make_float2(ua0.x, ub0.x);
        p0[1*PSTRIDE] = make_float2(ua0.y, ub0.y);
        p0[2*PSTRIDE] = make_float2(ua0.z, ub0.z);
        p0[3*PSTRIDE] = make_float2(ua0.w, ub0.w);
        p1[0*PSTRIDE] = make_float2(ua1.x, ub1.x);
        p1[1*PSTRIDE] = make_float2(ua1.y, ub1.y);
        p1[2*PSTRIDE] = make_float2(ua1.z, ub1.z);
        p1[3*PSTRIDE] = make_float2(ua1.w, ub1.w);
    }
    const float pa2 = sum4(ua0) + sum4(ua1);
    const float pb2 = sum4(ub0) + sum4(ub1);
    float s1a = red8(pa2), s1b = red8(pb2);
    const float xa2 = __shfl_sync(0xffffffffu, pick4(ua0, i1 & 3), dq_own, 8);
    const float xb2 = __shfl_sync(0xffffffffu, pick4(ub1, i1 & 3), dq_own, 8);
    {
        float ps = red32(pa2 + pb2);
        float dd = red32((q == 0) ? (xa2 + xb2) : 0.f);
        if ((t & 31) == 0) { Tw[t >> 5] = ps; Dw[t >> 5] = dd; }
    }

    // ================= Matrix 1: Phase 3 (emit) =================
    {
        const float4 c0 = *(const float4*)(Cvec + ib);
        const float4 c1 = *(const float4*)(Cvec + ib + 32);
        float4 oA0, oA1, oB0, oB1;
        oA0.x=cA+c0.x+va0.x; oA0.y=cA+c0.y+va0.y; oA0.z=cA+c0.z+va0.z; oA0.w=cA+c0.w+va0.w;
        oA1.x=cA+c1.x+va1.x; oA1.y=cA+c1.y+va1.y; oA1.z=cA+c1.z+va1.z; oA1.w=cA+c1.w+va1.w;
        oB0.x=cB+c0.x+vb0.x; oB0.y=cB+c0.y+vb0.y; oB0.z=cB+c0.z+vb0.z; oB0.w=cB+c0.w+vb0.w;
        oB1.x=cB+c1.x+vb1.x; oB1.y=cB+c1.y+vb1.y; oB1.z=cB+c1.z+vb1.z; oB1.w=cB+c1.w+vb1.w;
        const int dd = i1 - ib;
        if (dd >= 0 && dd < 4) { (&oA0.x)[dd] += evA; (&oB1.x)[dd] += evB; }
        float* orow = out + (size_t)blockIdx.x * 4096;
        *(float4*)(orow + i1 * 64 + ib)             = oA0;
        *(float4*)(orow + i1 * 64 + ib + 32)        = oA1;
        *(float4*)(orow + (i1 + 32) * 64 + ib)      = oB0;
        *(float4*)(orow + (i1 + 32) * 64 + ib + 32) = oB1;
    }
    __syncthreads();                                   // bar 3 (P2, Tw, Dw ready)

    // ================= Matrix 2: Phase 2 =================
    float T2, D2;
    {
        const float4 t0 = *(const float4*)Tw, t1 = *(const float4*)(Tw + 4);
        const float4 d0 = *(const float4*)Dw, d1 = *(const float4*)(Dw + 4);
        T2 = sum4(t0) + sum4(t1);
        D2 = sum4(d0) + sum4(d1);
    }
    const float gT2 = ws[14]*T2 + ws[4]*D2;
    const float gE2 = ws[11]*T2 + ws[2]*D2;

    float s2a, s2b;
    {
        const float2* pa0 = P + (size_t)i1 * PSTRIDE + ib;
        const float2* pb0 = P + (size_t)(i1 + 32) * PSTRIDE + ib;
        float2 q0 = pa0[0], q1 = pa0[1], q2 = pa0[2], q3 = pa0[3];
        s2a = ((q0.x+q1.x)+(q2.x+q3.x)) + ((q0.y+q1.y)+(q2.y+q3.y));
        ua0.x=w8v*ua0.x+w6v*q0.x;  ua1.x=w8v*ua1.x+w6v*q0.y;
        ua0.y=w8v*ua0.y+w6v*q1.x;  ua1.y=w8v*ua1.y+w6v*q1.y;
        ua0.z=w8v*ua0.z+w6v*q2.x;  ua1.z=w8v*ua1.z+w6v*q2.y;
        ua0.w=w8v*ua0.w+w6v*q3.x;  ua1.w=w8v*ua1.w+w6v*q3.y;
        q0 = pb0[0]; q1 = pb0[1]; q2 = pb0[2]; q3 = pb0[3];
        s2b = ((q0.x+q1.x)+(q2.x+q3.x)) + ((q0.y+q1.y)+(q2.y+q3.y));
        ub0.x=w8v*ub0.x+w6v*q0.x;  ub1.x=w8v*ub1.x+w6v*q0.y;
        ub0.y=w8v*ub0.y+w6v*q1.x;  ub1.y=w8v*ub1.y+w6v*q1.y;
        ub0.z=w8v*ub0.z+w6v*q2.x;  ub1.z=w8v*ub1.z+w6v*q2.y;
        ub0.w=w8v*ub0.w+w6v*q3.x;  ub1.w=w8v*ub1.w+w6v*q3.y;
    }
    s2a = red8(s2a); s2b = red8(s2b);

    const float cA2  = ws[12]*s1a + ws[13]*s2a + ws[3]*xa2 + gT2;
    const float evA2 = ws[5] *s1a + ws[9] *s2a + ws[0]*xa2 + gE2;
    const float cB2  = ws[12]*s1b + ws[13]*s2b + ws[3]*xb2 + gT2;
    const float evB2 = ws[5] *s1b + ws[9] *s2b + ws[0]*xb2 + gE2;
    if (q == 0) {
        Cvec[i1]      = ws[7]*s1a + ws[10]*s2a + ws[1]*xa2;
        Cvec[i1 + 32] = ws[7]*s1b + ws[10]*s2b + ws[1]*xb2;
    }
    __syncthreads();                                   // bar 4

    // ================= Matrix 2: Phase 3 (emit) =================
    {
        const float4 c0 = *(const float4*)(Cvec + ib);
        const float4 c1 = *(const float4*)(Cvec + ib + 32);
        float4 oA0, oA1, oB0, oB1;
        oA0.x=cA2+c0.x+ua0.x; oA0.y=cA2+c0.y+ua0.y; oA0.z=cA2+c0.z+ua0.z; oA0.w=cA2+c0.w+ua0.w;
        oA1.x=cA2+c1.x+ua1.x; oA1.y=cA2+c1.y+ua1.y; oA1.z=cA2+c1.z+ua1.z; oA1.w=cA2+c1.w+ua1.w;
        oB0.x=cB2+c0.x+ub0.x; oB0.y=cB2+c0.y+ub0.y; oB0.z=cB2+c0.z+ub0.z; oB0.w=cB2+c0.w+ub0.w;
        oB1.x=cB2+c1.x+ub1.x; oB1.y=cB2+c1.y+ub1.y; oB1.z=cB2+c1.z+ub1.z; oB1.w=cB2+c1.w+ub1.w;
        const int dd = i1 - ib;
        if (dd >= 0 && dd < 4) { (&oA0.x)[dd] += evA2; (&oB1.x)[dd] += evB2; }
        float* orow = out + ((size_t)blockIdx.x + 512) * 4096;
        *(float4*)(orow + i1 * 64 + ib)             = oA0;
        *(float4*)(orow + i1 * 64 + ib + 32)        = oA1;
        *(float4*)(orow + (i1 + 32) * 64 + ib)      = oB0;
        *(float4*)(orow + (i1 + 32) * 64 + ib + 32) = oB1;
    }
}

extern "C" void kernel_launch(void* const* d_in, const int* in_sizes, int n_in,
                              void* d_out, int out_size)
{
    const float* X = (const float*)d_in[0];      // (1024, 4096) fp32
    const float* w = (const float*)d_in[1];      // (15,) fp32
    // d_in[2] = B (15,4096,4096) — unused: W fully determined by w via the
    // partition decomposition (validated R0-R5, rel_err ~4e-7).
    float* out = (float*)d_out;                  // (1024, 4096) fp32
    (void)in_sizes; (void)n_in; (void)out_size;

    sym_equiv_kernel<<<512, THREADS>>>(X, w, out);
}

// round 8
// speedup vs baseline: 1.1940x; 1.1940x over previous
#include <cuda_runtime.h>
#include <cuda_bf16.h>

#define THREADS 256
#define PSTRIDE 33       // float2 row stride of P: bankpair(c*33+r) = (c+r)%16

__global__ __launch_bounds__(THREADS, 6)
void sym_equiv_kernel(const float* __restrict__ X,
                      const float* __restrict__ w,
                      float* __restrict__ out)
{
    // P[c][r] = (X[r][c], X[r+32][c]),  c in [0,64), r in [0,32)
    __shared__ float2 P[64 * PSTRIDE];          // 16,896 B
    __shared__ float Cvec[64];
    __shared__ __align__(16) float Tw[8];
    __shared__ __align__(16) float Dw[8];
    __shared__ float ws[15];

    const int t  = threadIdx.x;
    const int b  = blockIdx.x;
    const int i1 = t >> 3;              // owns rows i1 and i1+32  (i1 in 0..31)
    const int q  = t & 7;
    const int ib = q << 2;              // owns cols [ib,ib+4) and [ib+32,ib+36)

    if (t < 15) ws[t] = w[t];

    // ---- Phase 1: 4 coalesced float4 loads; 8 paired STS.64; r1/T reductions.
    const float* base = X + (size_t)b * 4096;
    float4 va0 = *(const float4*)(base + i1 * 64 + ib);
    float4 va1 = *(const float4*)(base + i1 * 64 + ib + 32);
    float4 vb0 = *(const float4*)(base + (i1 + 32) * 64 + ib);
    float4 vb1 = *(const float4*)(base + (i1 + 32) * 64 + ib + 32);

    {
        float2* p0 = P + (size_t)ib * PSTRIDE + i1;          // cols ib..ib+3
        float2* p1 = P + (size_t)(ib + 32) * PSTRIDE + i1;   // cols ib+32..+35
        p0[0*PSTRIDE] = make_float2(va0.x, vb0.x);
        p0[1*PSTRIDE] = make_float2(va0.y, vb0.y);
        p0[2*PSTRIDE] = make_float2(va0.z, vb0.z);
        p0[3*PSTRIDE] = make_float2(va0.w, vb0.w);
        p1[0*PSTRIDE] = make_float2(va1.x, vb1.x);
        p1[1*PSTRIDE] = make_float2(va1.y, vb1.y);
        p1[2*PSTRIDE] = make_float2(va1.z, vb1.z);
        p1[3*PSTRIDE] = make_float2(va1.w, vb1.w);
    }

    const float pa = (va0.x + va0.y + va0.z + va0.w) + (va1.x + va1.y + va1.z + va1.w);
    const float pb = (vb0.x + vb0.y + vb0.z + vb0.w) + (vb1.x + vb1.y + vb1.z + vb1.w);
    float r1a = pa, r1b = pb;
    r1a += __shfl_xor_sync(0xffffffffu, r1a, 1, 8);
    r1a += __shfl_xor_sync(0xffffffffu, r1a, 2, 8);
    r1a += __shfl_xor_sync(0xffffffffu, r1a, 4, 8);
    r1b += __shfl_xor_sync(0xffffffffu, r1b, 1, 8);
    r1b += __shfl_xor_sync(0xffffffffu, r1b, 2, 8);
    r1b += __shfl_xor_sync(0xffffffffu, r1b, 4, 8);

    float ps = pa + pb;
    #pragma unroll
    for (int o = 16; o > 0; o >>= 1) ps += __shfl_xor_sync(0xffffffffu, ps, o);
    if ((t & 31) == 0) Tw[t >> 5] = ps;

    __syncthreads();                    // (1) P, Tw ready

    // ---- Phase 2: 8 LDS.64 transpose reads (every byte used), fused with
    //      the w8*X + w6*X^T fold and the column-sum (r2) partials.
    const float w8v = ws[8], w6v = ws[6];
    float r2a, r2b;
    {
        const float2* pa0 = P + (size_t)i1 * PSTRIDE + ib;        // col i1
        const float2* pb0 = P + (size_t)(i1 + 32) * PSTRIDE + ib; // col i1+32
        float2 q0 = pa0[0], q1 = pa0[1], q2 = pa0[2], q3 = pa0[3];
        r2a = ((q0.x + q1.x) + (q2.x + q3.x)) + ((q0.y + q1.y) + (q2.y + q3.y));
        va0.x = w8v*va0.x + w6v*q0.x;  va1.x = w8v*va1.x + w6v*q0.y;
        va0.y = w8v*va0.y + w6v*q1.x;  va1.y = w8v*va1.y + w6v*q1.y;
        va0.z = w8v*va0.z + w6v*q2.x;  va1.z = w8v*va1.z + w6v*q2.y;
        va0.w = w8v*va0.w + w6v*q3.x;  va1.w = w8v*va1.w + w6v*q3.y;
        q0 = pb0[0]; q1 = pb0[1]; q2 = pb0[2]; q3 = pb0[3];
        r2b = ((q0.x + q1.x) + (q2.x + q3.x)) + ((q0.y + q1.y) + (q2.y + q3.y));
        vb0.x = w8v*vb0.x + w6v*q0.x;  vb1.x = w8v*vb1.x + w6v*q0.y;
        vb0.y = w8v*vb0.y + w6v*q1.x;  vb1.y = w8v*vb1.y + w6v*q1.y;
        vb0.z = w8v*vb0.z + w6v*q2.x;  vb1.z = w8v*vb1.z + w6v*q2.y;
        vb0.w = w8v*vb0.w + w6v*q3.x;  vb1.w = w8v*vb1.w + w6v*q3.y;
    }
    // the 8 row-mates' chunks tile all 64 rows -> width-8 reduce = full column sums
    r2a += __shfl_xor_sync(0xffffffffu, r2a, 1, 8);
    r2a += __shfl_xor_sync(0xffffffffu, r2a, 2, 8);
    r2a += __shfl_xor_sync(0xffffffffu, r2a, 4, 8);
    r2b += __shfl_xor_sync(0xffffffffu, r2b, 1, 8);
    r2b += __shfl_xor_sync(0xffffffffu, r2b, 2, 8);
    r2b += __shfl_xor_sync(0xffffffffu, r2b, 4, 8);

    const float xa = P[(size_t)i1 * PSTRIDE + i1].x;          // X[i1][i1]
    const float xb = P[(size_t)(i1 + 32) * PSTRIDE + i1].y;   // X[i1+32][i1+32]

    float dq = (q == 0) ? (xa + xb) : 0.f;    // trace partial per warp
    #pragma unroll
    for (int o = 16; o > 0; o >>= 1) dq += __shfl_xor_sync(0xffffffffu, dq, o);
    if ((t & 31) == 0) Dw[t >> 5] = dq;

    // weight folding (partition map from _set_partitions([0,1,2,3]) order)
    const float aA  = ws[12]*r1a + ws[13]*r2a + ws[3]*xa;     // row i1
    const float eA  = ws[5] *r1a + ws[9] *r2a + ws[0]*xa;
    const float aB  = ws[12]*r1b + ws[13]*r2b + ws[3]*xb;     // row i1+32
    const float eB  = ws[5] *r1b + ws[9] *r2b + ws[0]*xb;
    if (q == 0) {
        Cvec[i1]      = ws[7]*r1a + ws[10]*r2a + ws[1]*xa;
        Cvec[i1 + 32] = ws[7]*r1b + ws[10]*r2b + ws[1]*xb;
    }

    __syncthreads();                    // (2) Cvec, Dw ready

    // ---- Phase 3: close with T, D (float4 reads); emit 16 outputs.
    float T, D;
    {
        const float4 t0 = *(const float4*)Tw, t1 = *(const float4*)(Tw + 4);
        const float4 d0 = *(const float4*)Dw, d1 = *(const float4*)(Dw + 4);
        T = ((t0.x + t0.y) + (t0.z + t0.w)) + ((t1.x + t1.y) + (t1.z + t1.w));
        D = ((d0.x + d0.y) + (d0.z + d0.w)) + ((d1.x + d1.y) + (d1.z + d1.w));
    }
    const float gT = ws[14]*T + ws[4]*D;       // constant part
    const float gE = ws[11]*T + ws[2]*D;       // diagonal constant part
    const float cA = aA + gT, cB = aB + gT;
    const float evA = eA + gE, evB = eB + gE;

    const float4 c0 = *(const float4*)(Cvec + ib);
    const float4 c1 = *(const float4*)(Cvec + ib + 32);

    float4 oA0, oA1, oB0, oB1;
    oA0.x = cA + c0.x + va0.x;  oA0.y = cA + c0.y + va0.y;
    oA0.z = cA + c0.z + va0.z;  oA0.w = cA + c0.w + va0.w;
    oA1.x = cA + c1.x + va1.x;  oA1.y = cA + c1.y + va1.y;
    oA1.z = cA + c1.z + va1.z;  oA1.w = cA + c1.w + va1.w;
    oB0.x = cB + c0.x + vb0.x;  oB0.y = cB + c0.y + vb0.y;
    oB0.z = cB + c0.z + vb0.z;  oB0.w = cB + c0.w + vb0.w;
    oB1.x = cB + c1.x + vb1.x;  oB1.y = cB + c1.y + vb1.y;
    oB1.z = cB + c1.z + vb1.z;  oB1.w = cB + c1.w + vb1.w;

    // diagonal corrections: row i1 diag col i1 (low half); row i1+32 diag
    // col i1+32 (high half). Both land in the thread with ib == (i1 & ~3).
    const int dd = i1 - ib;
    if (dd >= 0 && dd < 4) {
        (&oA0.x)[dd] += evA;
        (&oB1.x)[dd] += evB;
    }

    float* orow = out + (size_t)b * 4096;
    *(float4*)(orow + i1 * 64 + ib)             = oA0;
    *(float4*)(orow + i1 * 64 + ib + 32)        = oA1;
    *(float4*)(orow + (i1 + 32) * 64 + ib)      = oB0;
    *(float4*)(orow + (i1 + 32) * 64 + ib + 32) = oB1;
}

extern "C" void kernel_launch(void* const* d_in, const int* in_sizes, int n_in,
                              void* d_out, int out_size)
{
    const float* X = (const float*)d_in[0];      // (1024, 4096) fp32
    const float* w = (const float*)d_in[1];      // (15,) fp32
    // d_in[2] = B (15,4096,4096) — unused: W is fully determined by w via the
    // partition-structure decomposition (validated R0-R6, rel_err ~4e-7).
    float* out = (float*)d_out;                  // (1024, 4096) fp32
    (void)in_sizes; (void)n_in; (void)out_size;

    sym_equiv_kernel<<<1024, THREADS>>>(X, w, out);
}